// round 2
// baseline (speedup 1.0000x reference)
#include <cuda_runtime.h>
#include <cstdint>

// =====================================================================
// QuantLinear: W8A8 quantized linear via int8 tensor cores (mma.sync).
//   Wq: row-wise symmetric s8, scale = absmax/127, plus row-sum.
//   Xq: per-token asymmetric u8, scale = (max-min)/255, zp = round(-min/s).
//   acc[m,n] = sum_k Xq[m,k]*Wq[n,k]   (exact s32, u8 x s8 IMMA)
//   Y = (acc - zp[m]*rowsumW[n]) * sa[m]*sw[n] + bias[n]
// Only base-sm_103 features: cp.async, ldmatrix, mma.sync (no tcgen05).
// =====================================================================

static constexpr int M_MAX = 8192;
static constexpr int N_MAX = 4096;
static constexpr int K_MAX = 4096;

// __device__ global scratch (allocation-free rule)
__device__ uint8_t g_xq[(size_t)M_MAX * K_MAX];
__device__ int8_t  g_wq[(size_t)N_MAX * K_MAX];
__device__ float   g_ascale[M_MAX];
__device__ float   g_azp[M_MAX];
__device__ float   g_wscale[N_MAX];
__device__ float   g_wrowsum[N_MAX];

// ======================= PTX helpers =======================

__device__ __forceinline__ uint32_t smem_to_u32(const void* p) {
    uint32_t a;
    asm("{ .reg .u64 t; cvta.to.shared.u64 t, %1; cvt.u32.u64 %0, t; }"
        : "=r"(a) : "l"(p));
    return a;
}

__device__ __forceinline__ void cp_async16(uint32_t smem_addr, const void* gptr) {
    asm volatile("cp.async.cg.shared.global [%0], [%1], 16;\n"
                 :: "r"(smem_addr), "l"(gptr) : "memory");
}

#define CP_ASYNC_COMMIT() asm volatile("cp.async.commit_group;\n" ::: "memory")
#define CP_ASYNC_WAIT(n)  asm volatile("cp.async.wait_group %0;\n" :: "n"(n) : "memory")

__device__ __forceinline__ void ldmatrix_x4(uint32_t& r0, uint32_t& r1,
                                            uint32_t& r2, uint32_t& r3,
                                            uint32_t addr) {
    asm volatile("ldmatrix.sync.aligned.m8n8.x4.shared.b16 {%0,%1,%2,%3}, [%4];"
                 : "=r"(r0), "=r"(r1), "=r"(r2), "=r"(r3) : "r"(addr));
}

__device__ __forceinline__ void imma16832(int& c0, int& c1, int& c2, int& c3,
                                          uint32_t a0, uint32_t a1, uint32_t a2, uint32_t a3,
                                          uint32_t b0, uint32_t b1) {
    asm volatile(
        "mma.sync.aligned.m16n8k32.row.col.s32.u8.s8.s32 "
        "{%0,%1,%2,%3}, {%4,%5,%6,%7}, {%8,%9}, {%0,%1,%2,%3};"
        : "+r"(c0), "+r"(c1), "+r"(c2), "+r"(c3)
        : "r"(a0), "r"(a1), "r"(a2), "r"(a3), "r"(b0), "r"(b1));
}

// ======================= quantization kernels =======================

__global__ void __launch_bounds__(256) quant_w_kernel(const float* __restrict__ w, int K) {
    const int n = blockIdx.x;
    const float4* row = reinterpret_cast<const float4*>(w + (size_t)n * K);
    const int nv = K >> 2;  // float4s per row

    float amax = 0.0f;
    for (int i = threadIdx.x; i < nv; i += blockDim.x) {
        float4 v = row[i];
        amax = fmaxf(amax, fmaxf(fmaxf(fabsf(v.x), fabsf(v.y)),
                                 fmaxf(fabsf(v.z), fabsf(v.w))));
    }
    #pragma unroll
    for (int o = 16; o; o >>= 1)
        amax = fmaxf(amax, __shfl_xor_sync(0xFFFFFFFF, amax, o));

    __shared__ float s_amax[8];
    __shared__ float s_scale;
    const int wid = threadIdx.x >> 5;
    if ((threadIdx.x & 31) == 0) s_amax[wid] = amax;
    __syncthreads();
    if (threadIdx.x == 0) {
        float a = s_amax[0];
        #pragma unroll
        for (int i = 1; i < 8; i++) a = fmaxf(a, s_amax[i]);
        float sc = (a > 0.0f) ? __fdiv_rn(a, 127.0f) : 1.0f;
        s_scale = sc;
        g_wscale[n] = sc;
    }
    __syncthreads();
    const float sc = s_scale;

    int rsum = 0;
    uchar4* dst = reinterpret_cast<uchar4*>(g_wq + (size_t)n * K);
    for (int i = threadIdx.x; i < nv; i += blockDim.x) {
        float4 v = row[i];
        int q0 = (int)fminf(fmaxf(rintf(__fdiv_rn(v.x, sc)), -127.0f), 127.0f);
        int q1 = (int)fminf(fmaxf(rintf(__fdiv_rn(v.y, sc)), -127.0f), 127.0f);
        int q2 = (int)fminf(fmaxf(rintf(__fdiv_rn(v.z, sc)), -127.0f), 127.0f);
        int q3 = (int)fminf(fmaxf(rintf(__fdiv_rn(v.w, sc)), -127.0f), 127.0f);
        rsum += q0 + q1 + q2 + q3;
        uchar4 b;
        b.x = (uint8_t)(int8_t)q0; b.y = (uint8_t)(int8_t)q1;
        b.z = (uint8_t)(int8_t)q2; b.w = (uint8_t)(int8_t)q3;
        dst[i] = b;
    }
    // reduce row sum
    #pragma unroll
    for (int o = 16; o; o >>= 1) rsum += __shfl_xor_sync(0xFFFFFFFF, rsum, o);
    __shared__ int s_sum[8];
    if ((threadIdx.x & 31) == 0) s_sum[wid] = rsum;
    __syncthreads();
    if (threadIdx.x == 0) {
        int t = s_sum[0];
        #pragma unroll
        for (int i = 1; i < 8; i++) t += s_sum[i];
        g_wrowsum[n] = (float)t;
    }
}

__global__ void __launch_bounds__(256) quant_x_kernel(const float* __restrict__ x, int K) {
    const int m = blockIdx.x;
    const float4* row = reinterpret_cast<const float4*>(x + (size_t)m * K);
    const int nv = K >> 2;

    float vmin = 3.0e38f, vmax = -3.0e38f;
    for (int i = threadIdx.x; i < nv; i += blockDim.x) {
        float4 v = row[i];
        vmin = fminf(vmin, fminf(fminf(v.x, v.y), fminf(v.z, v.w)));
        vmax = fmaxf(vmax, fmaxf(fmaxf(v.x, v.y), fmaxf(v.z, v.w)));
    }
    #pragma unroll
    for (int o = 16; o; o >>= 1) {
        vmin = fminf(vmin, __shfl_xor_sync(0xFFFFFFFF, vmin, o));
        vmax = fmaxf(vmax, __shfl_xor_sync(0xFFFFFFFF, vmax, o));
    }
    __shared__ float s_min[8], s_max[8];
    __shared__ float s_scale, s_zp;
    const int wid = threadIdx.x >> 5;
    if ((threadIdx.x & 31) == 0) { s_min[wid] = vmin; s_max[wid] = vmax; }
    __syncthreads();
    if (threadIdx.x == 0) {
        float mn = s_min[0], mx = s_max[0];
        #pragma unroll
        for (int i = 1; i < 8; i++) { mn = fminf(mn, s_min[i]); mx = fmaxf(mx, s_max[i]); }
        float rng = mx - mn;
        float sc = (rng > 0.0f) ? __fdiv_rn(rng, 255.0f) : 1.0f;
        float zp = rintf(__fdiv_rn(-mn, sc));
        s_scale = sc; s_zp = zp;
        g_ascale[m] = sc;
        g_azp[m] = zp;
    }
    __syncthreads();
    const float sc = s_scale, zp = s_zp;

    uchar4* dst = reinterpret_cast<uchar4*>(g_xq + (size_t)m * K);
    for (int i = threadIdx.x; i < nv; i += blockDim.x) {
        float4 v = row[i];
        float q0 = fminf(fmaxf(rintf(__fdiv_rn(v.x, sc)) + zp, 0.0f), 255.0f);
        float q1 = fminf(fmaxf(rintf(__fdiv_rn(v.y, sc)) + zp, 0.0f), 255.0f);
        float q2 = fminf(fmaxf(rintf(__fdiv_rn(v.z, sc)) + zp, 0.0f), 255.0f);
        float q3 = fminf(fmaxf(rintf(__fdiv_rn(v.w, sc)) + zp, 0.0f), 255.0f);
        uchar4 b;
        b.x = (uint8_t)q0; b.y = (uint8_t)q1; b.z = (uint8_t)q2; b.w = (uint8_t)q3;
        dst[i] = b;
    }
}

// ======================= int8 GEMM kernel =======================
// CTA tile 128(M) x 128(N), K-chunk 64 bytes. 256 threads = 8 warps,
// warp grid 2(M) x 4(N): each warp computes 64 x 32.
// 3-stage cp.async pipeline. Operand smem rows = 64B, 4 x 16B chunks,
// swizzle phys_chunk = c ^ ((row>>1)&3)  -> conflict-free ldmatrix.

static constexpr int STAGES = 3;
static constexpr int STAGE_BYTES = 16384;  // A 8K + B 8K
static constexpr int SMEM_BYTES = STAGES * STAGE_BYTES;  // 48KB

__global__ void __launch_bounds__(256)
gemm_kernel(float* __restrict__ out, const float* __restrict__ bias,
            int M, int N, int K) {
    __shared__ __align__(1024) uint8_t smem[SMEM_BYTES];
    const uint32_t smem_u32 = smem_to_u32(smem);

    const int tid  = threadIdx.x;
    const int lane = tid & 31;
    const int wid  = tid >> 5;
    const int m0 = blockIdx.y * 128;
    const int n0 = blockIdx.x * 128;
    const int warp_m = (wid >> 2) * 64;   // 0 or 64
    const int warp_n = (wid & 3) * 32;    // 0,32,64,96

    const int KT = K >> 6;   // number of 64B K-chunks

    const uint8_t* gA = g_xq + (size_t)m0 * K;
    const uint8_t* gB = reinterpret_cast<const uint8_t*>(g_wq) + (size_t)n0 * K;

    // copy mapping: idx -> row = idx>>2, chunk = idx&3
    const int cr0 = tid >> 2, cc0 = tid & 3;
    const int cswz0 = cc0 ^ ((cr0 >> 1) & 3);
    const int cr1 = (tid + 256) >> 2, cc1 = cc0;
    const int cswz1 = cc1 ^ ((cr1 >> 1) & 3);

    auto issue_stage = [&](int kt, int s) {
        if (kt < KT) {
            uint32_t sa = smem_u32 + s * STAGE_BYTES;
            uint32_t sb = sa + 8192;
            const uint8_t* ga = gA + (size_t)kt * 64;
            const uint8_t* gb = gB + (size_t)kt * 64;
            cp_async16(sa + cr0 * 64 + (cswz0 << 4), ga + (size_t)cr0 * K + cc0 * 16);
            cp_async16(sb + cr0 * 64 + (cswz0 << 4), gb + (size_t)cr0 * K + cc0 * 16);
            cp_async16(sa + cr1 * 64 + (cswz1 << 4), ga + (size_t)cr1 * K + cc1 * 16);
            cp_async16(sb + cr1 * 64 + (cswz1 << 4), gb + (size_t)cr1 * K + cc1 * 16);
        }
        CP_ASYNC_COMMIT();
    };

    // ldmatrix per-lane geometry
    const int a_row = lane & 15;            // local row within 16-row frag
    const int a_cs  = lane >> 4;            // which 16B half of the 32B k-step
    const int a_swz = (a_row >> 1) & 3;
    const int b_row = (lane & 7) + ((lane >> 4) << 3);  // local n within 16
    const int b_cs  = (lane >> 3) & 1;
    const int b_swz = (b_row >> 1) & 3;

    int acc[4][4][4];
    #pragma unroll
    for (int i = 0; i < 4; i++)
        #pragma unroll
        for (int j = 0; j < 4; j++)
            #pragma unroll
            for (int r = 0; r < 4; r++) acc[i][j][r] = 0;

    // prologue
    #pragma unroll
    for (int s = 0; s < STAGES - 1; s++) issue_stage(s, s);

    for (int kt = 0; kt < KT; kt++) {
        CP_ASYNC_WAIT(STAGES - 2);
        __syncthreads();

        const int s = kt % STAGES;
        const uint32_t sa = smem_u32 + s * STAGE_BYTES;
        const uint32_t sb = sa + 8192;

        #pragma unroll
        for (int ks = 0; ks < 2; ks++) {
            // A fragments: 4 x m16
            uint32_t af[4][4];
            #pragma unroll
            for (int mf = 0; mf < 4; mf++) {
                uint32_t addr = sa + (warp_m + mf * 16 + a_row) * 64
                              + (((2 * ks + a_cs) ^ a_swz) << 4);
                ldmatrix_x4(af[mf][0], af[mf][1], af[mf][2], af[mf][3], addr);
            }
            // B fragments: 2 ldmatrix cover 4 x n8
            uint32_t bf[2][4];
            #pragma unroll
            for (int p = 0; p < 2; p++) {
                uint32_t addr = sb + (warp_n + p * 16 + b_row) * 64
                              + (((2 * ks + b_cs) ^ b_swz) << 4);
                ldmatrix_x4(bf[p][0], bf[p][1], bf[p][2], bf[p][3], addr);
            }
            #pragma unroll
            for (int mf = 0; mf < 4; mf++) {
                #pragma unroll
                for (int nf = 0; nf < 4; nf++) {
                    const int p = nf >> 1, h = (nf & 1) << 1;
                    imma16832(acc[mf][nf][0], acc[mf][nf][1],
                              acc[mf][nf][2], acc[mf][nf][3],
                              af[mf][0], af[mf][1], af[mf][2], af[mf][3],
                              bf[p][h], bf[p][h + 1]);
                }
            }
        }
        issue_stage(kt + STAGES - 1, (kt + STAGES - 1) % STAGES);
    }

    // ================= epilogue =================
    #pragma unroll
    for (int mf = 0; mf < 4; mf++) {
        const int gr0 = m0 + warp_m + mf * 16 + (lane >> 2);
        const int gr1 = gr0 + 8;
        const float sa0 = g_ascale[gr0], zp0 = g_azp[gr0];
        const float sa1 = g_ascale[gr1], zp1 = g_azp[gr1];
        #pragma unroll
        for (int nf = 0; nf < 4; nf++) {
            const int gc = n0 + warp_n + nf * 8 + 2 * (lane & 3);
            const float sw0 = g_wscale[gc],   sw1 = g_wscale[gc + 1];
            const float rs0 = g_wrowsum[gc],  rs1 = g_wrowsum[gc + 1];
            const float bb0 = bias[gc],       bb1 = bias[gc + 1];
            float2 v0, v1;
            v0.x = ((float)acc[mf][nf][0] - zp0 * rs0) * (sa0 * sw0) + bb0;
            v0.y = ((float)acc[mf][nf][1] - zp0 * rs1) * (sa0 * sw1) + bb1;
            v1.x = ((float)acc[mf][nf][2] - zp1 * rs0) * (sa1 * sw0) + bb0;
            v1.y = ((float)acc[mf][nf][3] - zp1 * rs1) * (sa1 * sw1) + bb1;
            *reinterpret_cast<float2*>(out + (size_t)gr0 * N + gc) = v0;
            *reinterpret_cast<float2*>(out + (size_t)gr1 * N + gc) = v1;
        }
    }
}

// ======================= launch =======================

extern "C" void kernel_launch(void* const* d_in, const int* in_sizes, int n_in,
                              void* d_out, int out_size) {
    const float* x    = (const float*)d_in[0];
    const float* w    = (const float*)d_in[1];
    const float* bias = (const float*)d_in[2];
    float* out        = (float*)d_out;

    const int N = in_sizes[2];          // 4096
    const int K = in_sizes[1] / N;      // 4096
    const int M = in_sizes[0] / K;      // 8192

    quant_w_kernel<<<N, 256>>>(w, K);
    quant_x_kernel<<<M, 256>>>(x, K);

    dim3 grid(N / 128, M / 128);
    gemm_kernel<<<grid, 256>>>(out, bias, M, N, K);
}